// round 15
// baseline (speedup 1.0000x reference)
#include <cuda_runtime.h>
#include <cuda_fp16.h>
#include <cstdint>

// YOLO decode layer: B=16, A=3, C=80, H=W=76.
// in  : (B, A*(C+5), H, W) fp32 = (16, 255, 76, 76)   ~94.3 MB
// out : (B, A, H, W, 7)    fp32                        ~7.8 MB
//
// R15: bulk-DMA staging. Each CTA (128 threads) covers 256 consecutive
// positions of one (b,a) plane. One elected thread issues 85 cp.async.bulk
// copies (1 KB per channel, L2::evict_last hint) into SMEM; mbarrier
// expect_tx = whole tile. Compute = R14 body (position-paired
// ex2.approx.f16x2 softmax sum, exact fp32 argmax with first-occurrence
// tie semantics) reading float2 from SMEM. This bypasses the per-thread
// LDG / L1tex wavefront-queue path that capped warm runs at ~6 TB/s.

constexpr int A_   = 3;
constexpr int C_   = 80;
constexpr int H_   = 76;
constexpr int W_   = 76;
constexpr int HW_  = H_ * W_;           // 5776
constexpr int NCH_ = C_ + 5;            // 85
constexpr int B_   = 16;
constexpr int NPLANES = B_ * A_;        // 48
constexpr int TILE = 256;               // positions per CTA
constexpr int TILES_PER_PLANE = (HW_ + TILE - 1) / TILE;  // 23 (last = 144)
constexpr int NCTAS = NPLANES * TILES_PER_PLANE;          // 1104
constexpr int SMEM_BYTES = NCH_ * TILE * 4;               // 87040

__device__ __forceinline__ float fsig(float x) {
    return __fdividef(1.0f, 1.0f + __expf(-x));
}

__device__ __forceinline__ uint32_t pack_h2(float x, float y) {
    uint32_t d;
    asm("cvt.rn.f16x2.f32 %0, %1, %2;" : "=r"(d) : "f"(y), "f"(x));
    return d;
}
__device__ __forceinline__ uint32_t ex2_h2(uint32_t x) {
    uint32_t d;
    asm("ex2.approx.f16x2 %0, %1;" : "=r"(d) : "r"(x));
    return d;
}
__device__ __forceinline__ uint32_t hadd2(uint32_t a, uint32_t b) {
    uint32_t d;
    asm("add.rn.f16x2 %0, %1, %2;" : "=r"(d) : "r"(a), "r"(b));
    return d;
}
__device__ __forceinline__ void st_cs2(float2* p, float a, float b) {
    asm volatile("st.global.cs.v2.f32 [%0], {%1,%2};" :: "l"(p), "f"(a), "f"(b));
}

__device__ __forceinline__ uint32_t smem_u32(const void* p) {
    uint32_t a;
    asm("{ .reg .u64 t; cvta.to.shared.u64 t, %1; cvt.u32.u64 %0, t; }"
        : "=r"(a) : "l"(p));
    return a;
}

__device__ __forceinline__ void bulk_g2s(uint32_t dst, const void* src,
                                         uint32_t bytes, uint32_t mbar,
                                         uint64_t pol) {
    asm volatile(
        "cp.async.bulk.shared::cta.global.mbarrier::complete_tx::bytes"
        ".L2::cache_hint [%0], [%1], %2, [%3], %4;"
        :: "r"(dst), "l"(src), "r"(bytes), "r"(mbar), "l"(pol) : "memory");
}

__global__ void __launch_bounds__(128) yolo_kernel(
    const float* __restrict__ in,
    const float* __restrict__ anchors,
    float* __restrict__ out)
{
    extern __shared__ float sm[];               // [NCH_][TILE]
    __shared__ __align__(8) unsigned long long mbar_store;

    int cta = blockIdx.x;
    int n   = cta / TILES_PER_PLANE;            // plane (b,a), 0..47
    int t   = cta - n * TILES_PER_PLANE;
    int p0  = t * TILE;
    int cnt = min(TILE, HW_ - p0);              // 256 or 144

    int tid = threadIdx.x;
    uint32_t mbar = smem_u32(&mbar_store);

    uint64_t pol;
    asm("createpolicy.fractional.L2::evict_last.b64 %0, 1.0;" : "=l"(pol));

    if (tid == 0) {
        asm volatile("mbarrier.init.shared.b64 [%0], 1;" :: "r"(mbar) : "memory");
    }
    __syncthreads();

    if (tid == 0) {
        uint32_t seg = (uint32_t)cnt * 4u;
        uint32_t total = seg * NCH_;
        asm volatile("mbarrier.arrive.expect_tx.shared.b64 _, [%0], %1;"
                     :: "r"(mbar), "r"(total) : "memory");
        const float* src = in + (size_t)n * NCH_ * HW_ + p0;
        uint32_t dst = smem_u32(sm);
        #pragma unroll 5
        for (int ch = 0; ch < NCH_; ++ch)
            bulk_g2s(dst + (uint32_t)ch * (TILE * 4), src + (size_t)ch * HW_,
                     seg, mbar, pol);
    }

    // wait for the whole tile
    {
        uint32_t done;
        asm volatile(
            "{\n\t.reg .pred p;\n\t"
            "mbarrier.try_wait.parity.acquire.cta.shared::cta.b64 p, [%1], 0;\n\t"
            "selp.b32 %0, 1, 0, p;\n\t}"
            : "=r"(done) : "r"(mbar) : "memory");
        while (!done) {
            asm volatile(
                "{\n\t.reg .pred p;\n\t"
                "mbarrier.try_wait.parity.acquire.cta.shared::cta.b64 p, [%1], 0, 0x989680;\n\t"
                "selp.b32 %0, 1, 0, p;\n\t}"
                : "=r"(done) : "r"(mbar) : "memory");
        }
    }

    if (2 * tid >= cnt) return;                 // tail tile: 72 active threads

    int a = n % A_;
    float aw = anchors[2 * a + 0];
    float ah = anchors[2 * a + 1];

    int hw = p0 + 2 * tid;                      // even; pair stays in one row
    int gy = hw / W_;
    int gx = hw - gy * W_;

    const float2* s2 = reinterpret_cast<const float2*>(sm) + tid;  // [ch][pair]
    constexpr int CH_STRIDE2 = TILE / 2;        // float2 per channel row

    float2 r0 = s2[0 * CH_STRIDE2];
    float2 r1 = s2[1 * CH_STRIDE2];
    float2 r2 = s2[2 * CH_STRIDE2];
    float2 r3 = s2[3 * CH_STRIDE2];
    float2 r4 = s2[4 * CH_STRIDE2];

    // class loop: exact fp32 max/argmax (sequential, strict > keeps the
    // first index on exact ties = jnp.argmax semantics); softmax sum via
    // ex2.approx.f16x2, both positions packed per instruction.
    const float K = 1.4426950408889634f;        // log2(e)
    float m0 = -1e30f, m1 = -1e30f;
    int  id0 = 0, id1 = 0;
    uint32_t accA = 0u, accB = 0u;

    const float2* cbs = s2 + 5 * CH_STRIDE2;
    #pragma unroll 8
    for (int ch = 0; ch < C_; ch += 2) {
        float2 ca = cbs[(size_t)ch * CH_STRIDE2];
        float2 cc = cbs[(size_t)(ch + 1) * CH_STRIDE2];

        if (ca.x > m0) { m0 = ca.x; id0 = ch; }
        if (cc.x > m0) { m0 = cc.x; id0 = ch + 1; }
        if (ca.y > m1) { m1 = ca.y; id1 = ch; }
        if (cc.y > m1) { m1 = cc.y; id1 = ch + 1; }

        accA = hadd2(accA, ex2_h2(pack_h2(ca.x * K, ca.y * K)));
        accB = hadd2(accB, ex2_h2(pack_h2(cc.x * K, cc.y * K)));
    }

    uint32_t acc = hadd2(accA, accB);
    __half2 hs = *reinterpret_cast<__half2*>(&acc);
    float s0 = __low2float(hs);
    float s1 = __high2float(hs);

    const float invW = 1.0f / (float)W_;
    const float invH = 1.0f / (float)H_;

    float xv[2]  = {r0.x, r0.y};
    float yv[2]  = {r1.x, r1.y};
    float wv[2]  = {r2.x, r2.y};
    float hv[2]  = {r3.x, r3.y};
    float cv4[2] = {r4.x, r4.y};
    float mm[2]  = {m0, m1};
    float ss[2]  = {s0, s1};
    int   idv[2] = {id0, id1};

    float ov[14];
    #pragma unroll
    for (int j = 0; j < 2; ++j) {
        ov[j * 7 + 0] = (fsig(xv[j]) + (float)(gx + j)) * invW;
        ov[j * 7 + 1] = (fsig(yv[j]) + (float)gy) * invH;
        ov[j * 7 + 2] = __expf(wv[j]) * aw * invW;
        ov[j * 7 + 3] = __expf(hv[j]) * ah * invH;
        ov[j * 7 + 4] = fsig(cv4[j]);
        ov[j * 7 + 5] = __fdividef(__expf(mm[j]), ss[j]);
        ov[j * 7 + 6] = (float)idv[j];
    }

    // global pair index -> 7x STG.64 evict-first (14 contiguous floats)
    size_t gpair = (size_t)n * (HW_ / 2) + (p0 / 2) + tid;
    float2* o2 = reinterpret_cast<float2*>(out) + gpair * 7;
    #pragma unroll
    for (int q = 0; q < 7; ++q)
        st_cs2(o2 + q, ov[q * 2 + 0], ov[q * 2 + 1]);
}

extern "C" void kernel_launch(void* const* d_in, const int* in_sizes, int n_in,
                              void* d_out, int out_size) {
    const float* in      = (const float*)d_in[0];
    const float* anchors = (const float*)d_in[1];
    float* out           = (float*)d_out;
    (void)in_sizes; (void)n_in; (void)out_size;

    static bool attr_set = false;
    if (!attr_set) {
        cudaFuncSetAttribute(yolo_kernel,
                             cudaFuncAttributeMaxDynamicSharedMemorySize,
                             SMEM_BYTES);
        attr_set = true;
    }
    yolo_kernel<<<NCTAS, 128, SMEM_BYTES>>>(in, anchors, out);
}

// round 16
// speedup vs baseline: 1.6212x; 1.6212x over previous
#include <cuda_runtime.h>
#include <cuda_fp16.h>
#include <cstdint>

// YOLO decode layer: B=16, A=3, C=80, H=W=76.
// in  : (B, A*(C+5), H, W) fp32 = (16, 255, 76, 76)   ~94.3 MB
// out : (B, A, H, W, 7)    fp32                        ~7.8 MB
//
// R16: R14 semantics (float2 per thread = 2 positions; ex2.approx.f16x2
// softmax sum with fp32 log2e scaling; exact fp32 even/odd argmax chains
// + tie-aware merge) restructured for MLP: loads are front-batched into
// register arrays in two phases (45 then 40 outstanding LDG.64 per thread)
// so the ~250-cyc L2-hit latency is exposed once per phase instead of per
// unroll block. launch_bounds(128) w/o reg clamp lets ptxas keep ~115 regs.

constexpr int A_  = 3;
constexpr int C_  = 80;
constexpr int H_  = 76;
constexpr int W_  = 76;
constexpr int HW_ = H_ * W_;            // 5776
constexpr int NCH_ = C_ + 5;            // 85
constexpr int B_  = 16;
constexpr int PAIRS_PER_N = HW_ / 2;    // 2888
constexpr int NPAIRS = B_ * A_ * PAIRS_PER_N;  // 138624

__device__ __forceinline__ float fsig(float x) {
    return __fdividef(1.0f, 1.0f + __expf(-x));
}

__device__ __forceinline__ float2 ld_el(const float2* p, uint64_t pol) {
    float2 v;
    asm("ld.global.nc.L2::cache_hint.v2.f32 {%0,%1}, [%2], %3;"
        : "=f"(v.x), "=f"(v.y) : "l"(p), "l"(pol));
    return v;
}

__device__ __forceinline__ void st_cs2(float2* p, float a, float b) {
    asm volatile("st.global.cs.v2.f32 [%0], {%1,%2};" :: "l"(p), "f"(a), "f"(b));
}

__device__ __forceinline__ uint32_t pack_h2(float x, float y) {
    uint32_t d;
    asm("cvt.rn.f16x2.f32 %0, %1, %2;" : "=r"(d) : "f"(y), "f"(x));
    return d;
}
__device__ __forceinline__ uint32_t ex2_h2(uint32_t x) {
    uint32_t d;
    asm("ex2.approx.f16x2 %0, %1;" : "=r"(d) : "r"(x));
    return d;
}
__device__ __forceinline__ uint32_t hadd2(uint32_t a, uint32_t b) {
    uint32_t d;
    asm("add.rn.f16x2 %0, %1, %2;" : "=r"(d) : "r"(a), "r"(b));
    return d;
}

__global__ void __launch_bounds__(128) yolo_kernel(
    const float* __restrict__ in,
    const float* __restrict__ anchors,
    float* __restrict__ out)
{
    int g = blockIdx.x * blockDim.x + threadIdx.x;
    if (g >= NPAIRS) return;

    uint64_t pol;
    asm("createpolicy.fractional.L2::evict_last.b64 %0, 1.0;" : "=l"(pol));

    int n  = g / PAIRS_PER_N;           // flattened (b, a) index, 0..47
    int pr = g - n * PAIRS_PER_N;
    int hw = pr * 2;
    int a  = n % A_;

    float aw = anchors[2 * a + 0];
    float ah = anchors[2 * a + 1];

    int gy = hw / W_;                   // W even -> both positions same row
    int gx = hw - gy * W_;

    const float2* b2 = reinterpret_cast<const float2*>(in)
                     + (size_t)n * (NCH_ * PAIRS_PER_N) + pr;
    const float2* cb = b2 + 5 * PAIRS_PER_N;

    const float K = 1.4426950408889634f;   // log2(e), fp32 scaling (accuracy)
    float m0 = -1e30f, m1 = -1e30f;
    int  id0 = 0, id1 = 0;
    uint32_t accA = 0u, accB = 0u;

    // ---- phase A: front-batch box(5) + class channels 0..39 (45 LDG) ----
    float2 bx[5];
    #pragma unroll
    for (int c = 0; c < 5; ++c)
        bx[c] = ld_el(b2 + (size_t)c * PAIRS_PER_N, pol);

    float2 cl[40];
    #pragma unroll
    for (int i = 0; i < 40; ++i)
        cl[i] = ld_el(cb + (size_t)i * PAIRS_PER_N, pol);

    // consume phase A (channels ascending; even/odd chains, strict >)
    #pragma unroll
    for (int i = 0; i < 40; i += 2) {
        float2 ca = cl[i];
        float2 cc = cl[i + 1];
        if (ca.x > m0) { m0 = ca.x; id0 = i; }
        if (cc.x > m0) { m0 = cc.x; id0 = i + 1; }
        if (ca.y > m1) { m1 = ca.y; id1 = i; }
        if (cc.y > m1) { m1 = cc.y; id1 = i + 1; }
        accA = hadd2(accA, ex2_h2(pack_h2(ca.x * K, ca.y * K)));
        accB = hadd2(accB, ex2_h2(pack_h2(cc.x * K, cc.y * K)));
    }

    // ---- phase B: front-batch class channels 40..79 (40 LDG) ----
    #pragma unroll
    for (int i = 0; i < 40; ++i)
        cl[i] = ld_el(cb + (size_t)(40 + i) * PAIRS_PER_N, pol);

    #pragma unroll
    for (int i = 0; i < 40; i += 2) {
        float2 ca = cl[i];
        float2 cc = cl[i + 1];
        int ch = 40 + i;
        if (ca.x > m0) { m0 = ca.x; id0 = ch; }
        if (cc.x > m0) { m0 = cc.x; id0 = ch + 1; }
        if (ca.y > m1) { m1 = ca.y; id1 = ch; }
        if (cc.y > m1) { m1 = cc.y; id1 = ch + 1; }
        accA = hadd2(accA, ex2_h2(pack_h2(ca.x * K, ca.y * K)));
        accB = hadd2(accB, ex2_h2(pack_h2(cc.x * K, cc.y * K)));
    }

    uint32_t acc = hadd2(accA, accB);
    __half2 hs = *reinterpret_cast<__half2*>(&acc);
    float s0 = __low2float(hs);
    float s1 = __high2float(hs);

    const float invW = 1.0f / (float)W_;
    const float invH = 1.0f / (float)H_;

    float xv[2]  = {bx[0].x, bx[0].y};
    float yv[2]  = {bx[1].x, bx[1].y};
    float wv[2]  = {bx[2].x, bx[2].y};
    float hv[2]  = {bx[3].x, bx[3].y};
    float cv4[2] = {bx[4].x, bx[4].y};
    float mm[2]  = {m0, m1};
    float ss[2]  = {s0, s1};
    int   idv[2] = {id0, id1};

    float ov[14];
    #pragma unroll
    for (int j = 0; j < 2; ++j) {
        ov[j * 7 + 0] = (fsig(xv[j]) + (float)(gx + j)) * invW;
        ov[j * 7 + 1] = (fsig(yv[j]) + (float)gy) * invH;
        ov[j * 7 + 2] = __expf(wv[j]) * aw * invW;
        ov[j * 7 + 3] = __expf(hv[j]) * ah * invH;
        ov[j * 7 + 4] = fsig(cv4[j]);
        ov[j * 7 + 5] = __fdividef(__expf(mm[j]), ss[j]);
        ov[j * 7 + 6] = (float)idv[j];
    }

    // 14 contiguous floats per thread -> 7x STG.64 evict-first
    float2* o2 = reinterpret_cast<float2*>(out) + (size_t)g * 7;
    #pragma unroll
    for (int q = 0; q < 7; ++q)
        st_cs2(o2 + q, ov[q * 2 + 0], ov[q * 2 + 1]);
}

extern "C" void kernel_launch(void* const* d_in, const int* in_sizes, int n_in,
                              void* d_out, int out_size) {
    const float* in      = (const float*)d_in[0];
    const float* anchors = (const float*)d_in[1];
    float* out           = (float*)d_out;
    (void)in_sizes; (void)n_in; (void)out_size;

    int blocks = (NPAIRS + 127) / 128;  // 1083
    yolo_kernel<<<blocks, 128>>>(in, anchors, out);
}